// round 1
// baseline (speedup 1.0000x reference)
#include <cuda_runtime.h>

// Problem constants (fixed shapes from the reference setup)
#define NB   16      // batch
#define NT   128     // time
#define NHWC 25088   // 56*56*8 floats per frame
#define NS4  6272    // NHWC / 4 (float4 strips per frame)
#define NC   8       // channels
#define KCH  4       // time chunks
#define TC   (NT / KCH)          // 32 frames per chunk
#define NBLK_S ((NS4 + 255) / 256)  // 25 blocks over the spatial strip

// Scratch accumulators (no device allocation allowed -> __device__ globals)
__device__ double g_act[NB * NC];
__device__ double g_tot[NB * NC];
__device__ double g_ttv;

__global__ void init_kernel() {
    int i = threadIdx.x;
    if (i < NB * NC) { g_act[i] = 0.0; g_tot[i] = 0.0; }
    if (i == 0) g_ttv = 0.0;
}

__global__ __launch_bounds__(256) void reduce_kernel(const float4* __restrict__ x,
                                                     const int* __restrict__ length) {
    const int s4    = blockIdx.x * 256 + threadIdx.x;
    const bool live = (s4 < NS4);
    const int b     = blockIdx.z;
    const int chunk = blockIdx.y;
    const int len   = __ldg(&length[b]);
    const int t0    = chunk * TC;
    const float4* base = x + (size_t)b * NT * NS4 + (live ? s4 : 0);

    float ax = 0.f, ay = 0.f, az = 0.f, aw = 0.f;   // active sums (4 channels)
    float tx = 0.f, ty = 0.f, tz = 0.f, tw = 0.f;   // total sums
    float ttv = 0.f;
    float px = 0.f, py = 0.f, pz = 0.f, pw = 0.f;   // previous masked frame

    if (live) {
        if (t0 > 0 && (t0 - 1) < len) {
            float4 p = base[(size_t)(t0 - 1) * NS4];
            px = p.x; py = p.y; pz = p.z; pw = p.w;
        }
        #pragma unroll 4
        for (int t = t0; t < t0 + TC; ++t) {
            float4 v = base[(size_t)t * NS4];
            tx += v.x; ty += v.y; tz += v.z; tw += v.w;
            float cx, cy, cz, cw;
            if (t < len) {
                cx = v.x; cy = v.y; cz = v.z; cw = v.w;
                ax += v.x; ay += v.y; az += v.z; aw += v.w;
            } else {
                cx = 0.f; cy = 0.f; cz = 0.f; cw = 0.f;
            }
            if (t > 0) {   // skip only the global t=0 (chunk 0, first iter)
                ttv += fabsf(cx - px) + fabsf(cy - py) + fabsf(cz - pz) + fabsf(cw - pw);
            }
            px = cx; py = cy; pz = cz; pw = cw;
        }
    }

    // --- block reduction ---
    // Full-warp reduce for ttv
    #pragma unroll
    for (int m = 16; m >= 1; m >>= 1)
        ttv += __shfl_xor_sync(0xffffffffu, ttv, m);
    // Parity-preserving reduce: even lanes hold channels 0-3, odd lanes 4-7
    #pragma unroll
    for (int m = 2; m <= 16; m <<= 1) {
        ax += __shfl_xor_sync(0xffffffffu, ax, m);
        ay += __shfl_xor_sync(0xffffffffu, ay, m);
        az += __shfl_xor_sync(0xffffffffu, az, m);
        aw += __shfl_xor_sync(0xffffffffu, aw, m);
        tx += __shfl_xor_sync(0xffffffffu, tx, m);
        ty += __shfl_xor_sync(0xffffffffu, ty, m);
        tz += __shfl_xor_sync(0xffffffffu, tz, m);
        tw += __shfl_xor_sync(0xffffffffu, tw, m);
    }

    __shared__ float sh_a[8][NC];
    __shared__ float sh_t[8][NC];
    __shared__ float sh_v[8];
    const int w = threadIdx.x >> 5, lane = threadIdx.x & 31;
    if (lane == 0) {
        sh_a[w][0] = ax; sh_a[w][1] = ay; sh_a[w][2] = az; sh_a[w][3] = aw;
        sh_t[w][0] = tx; sh_t[w][1] = ty; sh_t[w][2] = tz; sh_t[w][3] = tw;
        sh_v[w] = ttv;
    } else if (lane == 1) {
        sh_a[w][4] = ax; sh_a[w][5] = ay; sh_a[w][6] = az; sh_a[w][7] = aw;
        sh_t[w][4] = tx; sh_t[w][5] = ty; sh_t[w][6] = tz; sh_t[w][7] = tw;
    }
    __syncthreads();

    if (threadIdx.x < NC) {
        const int c = threadIdx.x;
        float sa = 0.f, st = 0.f;
        #pragma unroll
        for (int w2 = 0; w2 < 8; ++w2) { sa += sh_a[w2][c]; st += sh_t[w2][c]; }
        atomicAdd(&g_act[b * NC + c], (double)sa);
        atomicAdd(&g_tot[b * NC + c], (double)st);
    } else if (threadIdx.x == NC) {
        float s = 0.f;
        #pragma unroll
        for (int w2 = 0; w2 < 8; ++w2) s += sh_v[w2];
        atomicAdd(&g_ttv, (double)s);
    }
}

__global__ void final_kernel(const float* __restrict__ count, float* __restrict__ out) {
    const int b = threadIdx.x;
    if (b >= NB) return;
    const float ttv = (float)g_ttv * 0.1f;
    float ah = 0.f, bh = 0.f;
    #pragma unroll
    for (int c = 0; c < NC; ++c) {
        const float a  = (float)g_act[b * NC + c];
        const float tt = (float)g_tot[b * NC + c];
        // huber(count, active_sum), delta = 1
        float e  = a - __ldg(&count[b * NC + c]);
        float ae = fabsf(e);
        ah += (ae <= 1.f) ? 0.5f * e * e : (ae - 0.5f);
        // huber(0, blank_sum)
        float eb  = tt - a;
        float aeb = fabsf(eb);
        bh += (aeb <= 1.f) ? 0.5f * eb * eb : (aeb - 0.5f);
    }
    out[b] = ah * (1.f / NC) + bh * (1.f / NC) + ttv;
}

extern "C" void kernel_launch(void* const* d_in, const int* in_sizes, int n_in,
                              void* d_out, int out_size) {
    const float* cam    = (const float*)d_in[0];
    const float* count  = (const float*)d_in[1];
    const int*   length = (const int*)d_in[2];
    float*       out    = (float*)d_out;

    init_kernel<<<1, 160>>>();
    dim3 grid(NBLK_S, KCH, NB);
    reduce_kernel<<<grid, 256>>>((const float4*)cam, length);
    final_kernel<<<1, 32>>>(count, out);
}